// round 14
// baseline (speedup 1.0000x reference)
#include <cuda_runtime.h>

#define NTOK 4128
#define WTOK 4096
#define NOBJ 8
#define NHEAD 8
#define DHEAD 40
#define QDIM 320
#define SCALE 0.15811388300841898f            // 1/sqrt(40)
#define QSCALE (0.15811388300841898f * 1.4426950408889634f)  // SCALE * log2(e)

// ---------------- scratch (static device globals; no allocation) ----------------
__device__ float g_q[NHEAD * NTOK * DHEAD];   // [h][n][c]  (token-permuted order)
__device__ float g_k[NHEAD * NTOK * DHEAD];
__device__ float g_v[NHEAD * NTOK * DHEAD];
__device__ float g_att[NTOK * QDIM];          // attention output before Wo (ORIGINAL order)
__device__ unsigned g_bits[WTOK];             // 8-bit object membership per pixel (original)
__device__ int g_perm[NTOK];                  // new -> old
__device__ int g_inv[NTOK];                   // old -> new
__device__ unsigned g_pb[NTOK];               // permuted bits (grounding = 0)

// ---------------- helpers ----------------
__device__ __forceinline__ unsigned f2tf(float x) {
    unsigned u; asm("cvt.rna.tf32.f32 %0, %1;" : "=r"(u) : "f"(x)); return u;
}
__device__ __forceinline__ float tfv(float x) {
    unsigned u; asm("cvt.rna.tf32.f32 %0, %1;" : "=r"(u) : "f"(x));
    return __uint_as_float(u);
}
__device__ __forceinline__ float ex2f(float x) {
    float y; asm("ex2.approx.ftz.f32 %0, %1;" : "=f"(y) : "f"(x)); return y;
}
__device__ __forceinline__ void mma8(float c[4], const unsigned a[4], unsigned b0, unsigned b1) {
    asm volatile(
        "mma.sync.aligned.m16n8k8.row.col.f32.tf32.tf32.f32 "
        "{%0,%1,%2,%3},{%4,%5,%6,%7},{%8,%9},{%0,%1,%2,%3};"
        : "+f"(c[0]), "+f"(c[1]), "+f"(c[2]), "+f"(c[3])
        : "r"(a[0]), "r"(a[1]), "r"(a[2]), "r"(a[3]), "r"(b0), "r"(b1));
}
__device__ __forceinline__ int kpos(int k) { return (k >> 3) * 8 + 2 * (k & 3) + ((k & 4) ? 1 : 0); }

// ---------------- mask bits ----------------
__global__ void bits_kernel(const float* __restrict__ am) {
    int w = blockIdx.x * 256 + threadIdx.x;
    if (w < WTOK) {
        unsigned b = 0;
#pragma unroll
        for (int o = 0; o < NOBJ; o++)
            if (am[o * WTOK + w] != 0.f) b |= (1u << o);
        g_bits[w] = b;
    }
}

// ---------------- counting sort of visual tokens by bit pattern (1 CTA) ----------------
__global__ __launch_bounds__(256) void sort_kernel() {
    __shared__ unsigned hist[256];
    __shared__ unsigned offs[256];
    const int tid = threadIdx.x;
    hist[tid] = 0;
    __syncthreads();
    for (int w = tid; w < WTOK; w += 256) atomicAdd(&hist[g_bits[w]], 1u);
    __syncthreads();
    if (tid == 0) {
        unsigned acc = 0;
        for (int i = 0; i < 256; i++) { offs[i] = acc; acc += hist[i]; }
    }
    __syncthreads();
    for (int w = tid; w < WTOK; w += 256) {
        unsigned b = g_bits[w];
        unsigned pos = atomicAdd(&offs[b], 1u);
        g_perm[pos] = w;
        g_inv[w] = (int)pos;
        g_pb[pos] = b;
    }
    for (int t = tid; t < NTOK - WTOK; t += 256) {
        g_perm[WTOK + t] = WTOK + t;
        g_inv[WTOK + t] = WTOK + t;
        g_pb[WTOK + t] = 0u;
    }
}

// ---------------- tf32 mma GEMM: 128x64 CTA tile, 3-stage (2 smem + 2 reg sets) ----------
struct GemmFrag { float c[8][4]; };

__device__ __forceinline__ void gemm320(
    const float* __restrict__ A, const float* __restrict__ B,
    int row0, int colbase, GemmFrag& F)
{
    __shared__ __align__(16) float As[2][128][18];
    __shared__ __align__(16) float Bs[2][64][18];

    const int tid = threadIdx.x;
    const int warp = tid >> 5, lane = tid & 31;
    const int g = lane >> 2, ctg = lane & 3;
    const int wr = warp * 16;

#pragma unroll
    for (int nt = 0; nt < 8; nt++) F.c[nt][0] = F.c[nt][1] = F.c[nt][2] = F.c[nt][3] = 0.f;

    const int ar = tid >> 2;              // A rows: ar, ar+64
    const int aq = (tid & 3) * 4;         // k-quad
    const int bn = tid & 63, bk0 = tid >> 6;

    float4 ra[2][2];
    float  rb[2][4];

    // prologue: chunks 0,1 in flight
#pragma unroll
    for (int s = 0; s < 2; s++) {
        const int k0 = s * 16;
#pragma unroll
        for (int i = 0; i < 2; i++) {
            int row = row0 + ar + i * 64;
            ra[s][i] = make_float4(0.f, 0.f, 0.f, 0.f);
            if (row < NTOK) ra[s][i] = *(const float4*)&A[row * QDIM + k0 + aq];
        }
#pragma unroll
        for (int j = 0; j < 4; j++)
            rb[s][j] = B[(k0 + bk0 + 4 * j) * QDIM + colbase + bn];
    }

    for (int kc = 0; kc < 20; kc++) {
        const int cs = kc & 1;
        // STS reg set cs -> smem stage cs
        {
            const int base = (aq >> 3) * 8 + ((aq & 4) ? 1 : 0);
#pragma unroll
            for (int i = 0; i < 2; i++) {
                As[cs][ar + i * 64][base + 0] = tfv(ra[cs][i].x);
                As[cs][ar + i * 64][base + 2] = tfv(ra[cs][i].y);
                As[cs][ar + i * 64][base + 4] = tfv(ra[cs][i].z);
                As[cs][ar + i * 64][base + 6] = tfv(ra[cs][i].w);
            }
#pragma unroll
            for (int j = 0; j < 4; j++)
                Bs[cs][bn][kpos(bk0 + 4 * j)] = tfv(rb[cs][j]);
        }
        __syncthreads();
        // issue LDG for chunk kc+2 into reg set cs (consumed 2 iterations later)
        if (kc + 2 < 20) {
            const int k0 = (kc + 2) * 16;
#pragma unroll
            for (int i = 0; i < 2; i++) {
                int row = row0 + ar + i * 64;
                ra[cs][i] = make_float4(0.f, 0.f, 0.f, 0.f);
                if (row < NTOK) ra[cs][i] = *(const float4*)&A[row * QDIM + k0 + aq];
            }
#pragma unroll
            for (int j = 0; j < 4; j++)
                rb[cs][j] = B[(k0 + bk0 + 4 * j) * QDIM + colbase + bn];
        }
        // compute smem stage cs
#pragma unroll
        for (int ks = 0; ks < 2; ks++) {
            uint2 aA = *(const uint2*)&As[cs][wr + g][ks * 8 + 2 * ctg];
            uint2 aB = *(const uint2*)&As[cs][wr + g + 8][ks * 8 + 2 * ctg];
            unsigned a[4] = { aA.x, aB.x, aA.y, aB.y };
#pragma unroll
            for (int nt = 0; nt < 8; nt++) {
                const uint2 b = *(const uint2*)&Bs[cs][nt * 8 + g][ks * 8 + 2 * ctg];
                mma8(F.c[nt], a, b.x, b.y);
            }
        }
    }
}

// ---------------- QKV via mma: scatter into permuted token order. grid (33,15) ----------
__global__ __launch_bounds__(256) void qkv_mma_kernel(
    const float* __restrict__ x,
    const float* __restrict__ Wq, const float* __restrict__ Wk, const float* __restrict__ Wv)
{
    const int by = blockIdx.y;
    const int wsel = by / 5;
    const int colbase = (by % 5) * 64;
    const float* W = (wsel == 0) ? Wq : (wsel == 1) ? Wk : Wv;
    float* dst = (wsel == 0) ? g_q : (wsel == 1) ? g_k : g_v;

    const int row0 = blockIdx.x * 128;
    GemmFrag F;
    gemm320(x, W, row0, colbase, F);

    const int lane = threadIdx.x & 31;
    const int g = lane >> 2, ctg = lane & 3;
    const int wr = (threadIdx.x >> 5) * 16;
    const int r0 = row0 + wr + g, r1 = r0 + 8;
    const int p0 = (r0 < NTOK) ? g_inv[r0] : 0;
    const int p1 = (r1 < NTOK) ? g_inv[r1] : 0;
#pragma unroll
    for (int nt = 0; nt < 8; nt++) {
        int col = colbase + nt * 8 + 2 * ctg;
        int h = col / DHEAD, cc = col % DHEAD;   // pair never straddles head
        if (r0 < NTOK) *(float2*)&dst[(h * NTOK + p0) * DHEAD + cc] = make_float2(F.c[nt][0], F.c[nt][1]);
        if (r1 < NTOK) *(float2*)&dst[(h * NTOK + p1) * DHEAD + cc] = make_float2(F.c[nt][2], F.c[nt][3]);
    }
}

// ---------------- output projection via mma (original order). grid (33,5) ----------------
__global__ __launch_bounds__(256) void proj_mma_kernel(
    const float* __restrict__ Wo, const float* __restrict__ bo, float* __restrict__ out)
{
    const int row0 = blockIdx.x * 128;
    const int colbase = blockIdx.y * 64;
    GemmFrag F;
    gemm320(g_att, Wo, row0, colbase, F);

    const int lane = threadIdx.x & 31;
    const int g = lane >> 2, ctg = lane & 3;
    const int wr = (threadIdx.x >> 5) * 16;
    const int r0 = row0 + wr + g, r1 = r0 + 8;
#pragma unroll
    for (int nt = 0; nt < 8; nt++) {
        int col = colbase + nt * 8 + 2 * ctg;
        float2 bias = *(const float2*)&bo[col];
        if (r0 < NTOK) *(float2*)&out[r0 * QDIM + col] =
            make_float2(F.c[nt][0] + bias.x, F.c[nt][1] + bias.y);
        if (r1 < NTOK) *(float2*)&out[r1 * QDIM + col] =
            make_float2(F.c[nt][2] + bias.x, F.c[nt][3] + bias.y);
    }
}

// ---------------- flash attention: permuted space, tile skip, db K/V, 1 bar/tile ----
__global__ __launch_bounds__(256, 2) void attn_kernel() {
    __shared__ __align__(16) float Ks[2][64][42];
    __shared__ __align__(16) float Vp[2][32][80];
    __shared__ __align__(8) unsigned kb_[2][64];
    __shared__ unsigned colp[2][2];

    const int tid  = threadIdx.x;
    const int warp = tid >> 5, lane = tid & 31;
    const int g    = lane >> 2, ctg = lane & 3;
    const int qb   = blockIdx.x, head = blockIdx.y;
    const int qr0  = qb * 128;
    const int wr0  = qr0 + warp * 16;
    const bool qvis = (qr0 < WTOK);

    const float* Q = g_q + head * NTOK * DHEAD;
    const float* K = g_k + head * NTOK * DHEAD;
    const float* V = g_v + head * NTOK * DHEAD;

    const int r0g = wr0 + g, r1g = r0g + 8;
    const int diagKt = wr0 >> 6;

    unsigned qa[5][4];
#pragma unroll
    for (int ks = 0; ks < 5; ks++) {
        int c0 = ks * 8 + ctg;
        float q00 = (r0g < NTOK) ? Q[r0g * DHEAD + c0]     : 0.f;
        float q10 = (r1g < NTOK) ? Q[r1g * DHEAD + c0]     : 0.f;
        float q01 = (r0g < NTOK) ? Q[r0g * DHEAD + c0 + 4] : 0.f;
        float q11 = (r1g < NTOK) ? Q[r1g * DHEAD + c0 + 4] : 0.f;
        qa[ks][0] = f2tf(q00 * QSCALE);
        qa[ks][1] = f2tf(q10 * QSCALE);
        qa[ks][2] = f2tf(q01 * QSCALE);
        qa[ks][3] = f2tf(q11 * QSCALE);
    }
    const unsigned rb0 = (r0g < WTOK) ? g_pb[r0g] : 0u;
    const unsigned rb1 = (r1g < WTOK) ? g_pb[r1g] : 0u;
    const unsigned warpOR = __reduce_or_sync(0xffffffffu, rb0 | rb1);

    float m0 = -1e30f, m1 = -1e30f, l0 = 0.f, l1 = 0.f;
    float O[5][4] = {};

    float4 kr[3], vr[3];
    unsigned kbreg = 0, cpart = 0;

    // ---- load tile 0 into regs ----
#pragma unroll
    for (int i = 0; i < 3; i++) {
        int u = tid + 256 * i;
        kr[i] = make_float4(0.f, 0.f, 0.f, 0.f);
        vr[i] = kr[i];
        if (u < 640) {
            int j = u / 10, c4 = (u % 10) * 4;
            if (j < NTOK) {
                kr[i] = *(const float4*)&K[j * DHEAD + c4];
                vr[i] = *(const float4*)&V[j * DHEAD + c4];
            }
        }
    }
    if (warp < 2) {
        kbreg = (tid < NTOK) ? g_pb[tid] : 0u;
        cpart = __reduce_or_sync(0xffffffffu, kbreg);
    }

    for (int kt = 0; kt < 65; kt++) {
        const int k0 = kt * 64;
        const bool kvis = (k0 < WTOK);
        const int st = kt & 1;

        // ---- STS regs -> stage st ----
#pragma unroll
        for (int i = 0; i < 3; i++) {
            int u = tid + 256 * i;
            if (u < 640) {
                int j = u / 10, c4 = (u % 10) * 4;
                int b8 = c4 >> 3;
                float* krp = &Ks[st][j][b8 * 8 + ((c4 & 4) ? 1 : 0)];
                krp[0] = tfv(kr[i].x); krp[2] = tfv(kr[i].y);
                krp[4] = tfv(kr[i].z); krp[6] = tfv(kr[i].w);
                float* vrp = &Vp[st][(j >> 3) * 4 + (j & 3)][c4 * 2 + ((j >> 2) & 1)];
                vrp[0] = tfv(vr[i].x); vrp[2] = tfv(vr[i].y);
                vrp[4] = tfv(vr[i].z); vrp[6] = tfv(vr[i].w);
            }
        }
        if (warp < 2) {
            kb_[st][warp * 32 + lane] = kbreg;
            if (lane == 0) colp[st][warp] = cpart;
        }
        __syncthreads();

        // ---- prefetch tile kt+1 -> regs (hidden behind compute) ----
        if (kt + 1 < 65) {
            const int nk0 = (kt + 1) * 64;
#pragma unroll
            for (int i = 0; i < 3; i++) {
                int u = tid + 256 * i;
                kr[i] = make_float4(0.f, 0.f, 0.f, 0.f);
                vr[i] = kr[i];
                if (u < 640) {
                    int j = u / 10, c4 = (u % 10) * 4;
                    int key = nk0 + j;
                    if (key < NTOK) {
                        kr[i] = *(const float4*)&K[key * DHEAD + c4];
                        vr[i] = *(const float4*)&V[key * DHEAD + c4];
                    }
                }
            }
            if (warp < 2) {
                int key = nk0 + warp * 32 + lane;
                kbreg = (key < NTOK) ? g_pb[key] : 0u;
                cpart = __reduce_or_sync(0xffffffffu, kbreg);
            }
        }

        // ---- exact-safe warp-level tile skip ----
        if (qvis && kvis && kt != diagKt && ((warpOR & (colp[st][0] | colp[st][1])) == 0u))
            continue;

        // ---- S = Q K^T ----
        float c[8][4];
#pragma unroll
        for (int nt = 0; nt < 8; nt++) { c[nt][0] = c[nt][1] = c[nt][2] = c[nt][3] = 0.f; }
#pragma unroll
        for (int nt = 0; nt < 8; nt++) {
#pragma unroll
            for (int ks = 0; ks < 5; ks++) {
                const uint2 b = *(const uint2*)&Ks[st][nt * 8 + g][ks * 8 + 2 * ctg];
                mma8(c[nt], qa[ks], b.x, b.y);
            }
        }

        // ---- mask ----
        if (qvis && kvis) {
            if (kt == diagKt) {
                const int ri0 = r0g - k0, ri1 = r1g - k0;
#pragma unroll
                for (int nt = 0; nt < 8; nt++) {
                    int j0 = nt * 8 + 2 * ctg;
                    uint2 cb = *(const uint2*)&kb_[st][j0];
                    if (!((rb0 & cb.x) || (ri0 == j0)))     c[nt][0] = -1e30f;
                    if (!((rb0 & cb.y) || (ri0 == j0 + 1))) c[nt][1] = -1e30f;
                    if (!((rb1 & cb.x) || (ri1 == j0)))     c[nt][2] = -1e30f;
                    if (!((rb1 & cb.y) || (ri1 == j0 + 1))) c[nt][3] = -1e30f;
                }
            } else {
#pragma unroll
                for (int nt = 0; nt < 8; nt++) {
                    uint2 cb = *(const uint2*)&kb_[st][nt * 8 + 2 * ctg];
                    if (!(rb0 & cb.x)) c[nt][0] = -1e30f;
                    if (!(rb0 & cb.y)) c[nt][1] = -1e30f;
                    if (!(rb1 & cb.x)) c[nt][2] = -1e30f;
                    if (!(rb1 & cb.y)) c[nt][3] = -1e30f;
                }
            }
        } else if (qvis) {
#pragma unroll
            for (int nt = 0; nt < 8; nt++) {
                int col0 = k0 + nt * 8 + 2 * ctg;
                int t0 = col0 - WTOK, t1 = t0 + 1;
                bool gr0 = (t0 >= 8 && t0 < 24), gr1 = (t1 >= 8 && t1 < 24);
                if (!((col0     < NTOK) && (gr0 || ((rb0 >> (t0 & 7)) & 1)))) c[nt][0] = -1e30f;
                if (!((col0 + 1 < NTOK) && (gr1 || ((rb0 >> (t1 & 7)) & 1)))) c[nt][1] = -1e30f;
                if (!((col0     < NTOK) && (gr0 || ((rb1 >> (t0 & 7)) & 1)))) c[nt][2] = -1e30f;
                if (!((col0 + 1 < NTOK) && (gr1 || ((rb1 >> (t1 & 7)) & 1)))) c[nt][3] = -1e30f;
            }
        } else if (kvis) {
            int t0 = r0g - WTOK, t1 = r1g - WTOK;
            bool gr0 = (t0 >= 8 && t0 < 24), gr1 = (t1 >= 8 && t1 < 24);
#pragma unroll
            for (int nt = 0; nt < 8; nt++) {
                uint2 cb = *(const uint2*)&kb_[st][nt * 8 + 2 * ctg];
                if (!(gr0 || ((cb.x >> (t0 & 7)) & 1))) c[nt][0] = -1e30f;
                if (!(gr1 || ((cb.x >> (t1 & 7)) & 1))) c[nt][2] = -1e30f;
                if (!(gr0 || ((cb.y >> (t0 & 7)) & 1))) c[nt][1] = -1e30f;
                if (!(gr1 || ((cb.y >> (t1 & 7)) & 1))) c[nt][3] = -1e30f;
            }
        } else {
#pragma unroll
            for (int nt = 0; nt < 8; nt++) {
                int col0 = k0 + nt * 8 + 2 * ctg;
                if (!(col0     < NTOK)) { c[nt][0] = -1e30f; c[nt][2] = -1e30f; }
                if (!(col0 + 1 < NTOK)) { c[nt][1] = -1e30f; c[nt][3] = -1e30f; }
            }
        }

        // ---- online softmax (base 2) ----
        float mx0 = c[0][0], mx1 = c[0][2];
#pragma unroll
        for (int nt = 0; nt < 8; nt++) {
            mx0 = fmaxf(mx0, fmaxf(c[nt][0], c[nt][1]));
            mx1 = fmaxf(mx1, fmaxf(c[nt][2], c[nt][3]));
        }
        mx0 = fmaxf(mx0, __shfl_xor_sync(0xffffffffu, mx0, 1));
        mx0 = fmaxf(mx0, __shfl_xor_sync(0xffffffffu, mx0, 2));
        mx1 = fmaxf(mx1, __shfl_xor_sync(0xffffffffu, mx1, 1));
        mx1 = fmaxf(mx1, __shfl_xor_sync(0xffffffffu, mx1, 2));

        float nm0 = fmaxf(m0, mx0), nm1 = fmaxf(m1, mx1);
        float f0 = ex2f(m0 - nm0), f1 = ex2f(m1 - nm1);
        m0 = nm0; m1 = nm1;

        float s0 = 0.f, s1 = 0.f;
#pragma unroll
        for (int nt = 0; nt < 8; nt++) {
            c[nt][0] = tfv(ex2f(c[nt][0] - nm0));
            c[nt][1] = tfv(ex2f(c[nt][1] - nm0));
            c[nt][2] = tfv(ex2f(c[nt][2] - nm1));
            c[nt][3] = tfv(ex2f(c[nt][3] - nm1));
            s0 += c[nt][0] + c[nt][1];
            s1 += c[nt][2] + c[nt][3];
        }
        s0 += __shfl_xor_sync(0xffffffffu, s0, 1);
        s0 += __shfl_xor_sync(0xffffffffu, s0, 2);
        s1 += __shfl_xor_sync(0xffffffffu, s1, 1);
        s1 += __shfl_xor_sync(0xffffffffu, s1, 2);
        l0 = l0 * f0 + s0;
        l1 = l1 * f1 + s1;

#pragma unroll
        for (int nt = 0; nt < 5; nt++) {
            O[nt][0] *= f0; O[nt][1] *= f0; O[nt][2] *= f1; O[nt][3] *= f1;
        }

        // ---- O += P V : C-layout -> A-layout via quad shuffles ----
        const int srcA = (lane & ~3) | (ctg >> 1);
        const int srcB = srcA + 2;
        const bool hi = (ctg & 1);
#pragma unroll
        for (int kk = 0; kk < 8; kk++) {
            float x0 = __shfl_sync(0xffffffffu, c[kk][0], srcA);
            float x1 = __shfl_sync(0xffffffffu, c[kk][1], srcA);
            float x2 = __shfl_sync(0xffffffffu, c[kk][2], srcA);
            float x3 = __shfl_sync(0xffffffffu, c[kk][3], srcA);
            float y0 = __shfl_sync(0xffffffffu, c[kk][0], srcB);
            float y1 = __shfl_sync(0xffffffffu, c[kk][1], srcB);
            float y2 = __shfl_sync(0xffffffffu, c[kk][2], srcB);
            float y3 = __shfl_sync(0xffffffffu, c[kk][3], srcB);
            unsigned a[4];
            a[0] = __float_as_uint(hi ? x1 : x0);
            a[1] = __float_as_uint(hi ? x3 : x2);
            a[2] = __float_as_uint(hi ? y1 : y0);
            a[3] = __float_as_uint(hi ? y3 : y2);
#pragma unroll
            for (int nt = 0; nt < 5; nt++) {
                const uint2 b = *(const uint2*)&Vp[st][kk * 4 + ctg][(nt * 8 + g) * 2];
                mma8(O[nt], a, b.x, b.y);
            }
        }
    }

    // ---- epilogue: gather back to original token order ----
    float il0 = 1.f / l0, il1 = 1.f / l1;
    const int o0 = (r0g < NTOK) ? g_perm[r0g] : 0;
    const int o1 = (r1g < NTOK) ? g_perm[r1g] : 0;
#pragma unroll
    for (int nt = 0; nt < 5; nt++) {
        int col = head * DHEAD + nt * 8 + 2 * ctg;
        if (r0g < NTOK) {
            float2 o = make_float2(O[nt][0] * il0, O[nt][1] * il0);
            *(float2*)&g_att[o0 * QDIM + col] = o;
        }
        if (r1g < NTOK) {
            float2 o = make_float2(O[nt][2] * il1, O[nt][3] * il1);
            *(float2*)&g_att[o1 * QDIM + col] = o;
        }
    }
}

// ---------------- launch ----------------
extern "C" void kernel_launch(void* const* d_in, const int* in_sizes, int n_in,
                              void* d_out, int out_size) {
    const float* x  = (const float*)d_in[0];
    const float* am = (const float*)d_in[1];
    const float* Wq = (const float*)d_in[2];
    const float* Wk = (const float*)d_in[3];
    const float* Wv = (const float*)d_in[4];
    const float* Wo = (const float*)d_in[5];
    const float* bo = (const float*)d_in[6];
    float* out = (float*)d_out;

    bits_kernel<<<16, 256>>>(am);
    sort_kernel<<<1, 256>>>();
    qkv_mma_kernel<<<dim3(33, 15), 256>>>(x, Wq, Wk, Wv);
    attn_kernel<<<dim3(33, NHEAD), 256>>>();
    proj_mma_kernel<<<dim3(33, 5), 256>>>(Wo, bo, out);
}

// round 17
// speedup vs baseline: 1.0780x; 1.0780x over previous
#include <cuda_runtime.h>

#define NTOK 4128
#define WTOK 4096
#define NOBJ 8
#define NHEAD 8
#define DHEAD 40
#define QDIM 320
#define SCALE 0.15811388300841898f            // 1/sqrt(40)
#define QSCALE (0.15811388300841898f * 1.4426950408889634f)  // SCALE * log2(e)

// ---------------- scratch (static device globals; no allocation) ----------------
__device__ float g_q[NHEAD * NTOK * DHEAD];   // [h][n][c]  (token-permuted order)
__device__ float g_k[NHEAD * NTOK * DHEAD];
__device__ float g_v[NHEAD * NTOK * DHEAD];
__device__ float g_att[NTOK * QDIM];          // attention output before Wo (ORIGINAL order)
__device__ unsigned g_bits[WTOK];             // 8-bit object membership per pixel (original)
__device__ int g_perm[NTOK];                  // new -> old
__device__ int g_inv[NTOK];                   // old -> new
__device__ unsigned g_pb[NTOK];               // permuted bits (grounding = 0)

// ---------------- helpers ----------------
__device__ __forceinline__ unsigned f2tf(float x) {
    unsigned u; asm("cvt.rna.tf32.f32 %0, %1;" : "=r"(u) : "f"(x)); return u;
}
__device__ __forceinline__ float tfv(float x) {
    unsigned u; asm("cvt.rna.tf32.f32 %0, %1;" : "=r"(u) : "f"(x));
    return __uint_as_float(u);
}
__device__ __forceinline__ float ex2f(float x) {
    float y; asm("ex2.approx.ftz.f32 %0, %1;" : "=f"(y) : "f"(x)); return y;
}
__device__ __forceinline__ void mma8(float c[4], const unsigned a[4], unsigned b0, unsigned b1) {
    asm volatile(
        "mma.sync.aligned.m16n8k8.row.col.f32.tf32.tf32.f32 "
        "{%0,%1,%2,%3},{%4,%5,%6,%7},{%8,%9},{%0,%1,%2,%3};"
        : "+f"(c[0]), "+f"(c[1]), "+f"(c[2]), "+f"(c[3])
        : "r"(a[0]), "r"(a[1]), "r"(a[2]), "r"(a[3]), "r"(b0), "r"(b1));
}
__device__ __forceinline__ int kpos(int k) { return (k >> 3) * 8 + 2 * (k & 3) + ((k & 4) ? 1 : 0); }

// ---------------- mask bits ----------------
__global__ void bits_kernel(const float* __restrict__ am) {
    int w = blockIdx.x * 256 + threadIdx.x;
    if (w < WTOK) {
        unsigned b = 0;
#pragma unroll
        for (int o = 0; o < NOBJ; o++)
            if (am[o * WTOK + w] != 0.f) b |= (1u << o);
        g_bits[w] = b;
    }
}

// ---------------- counting sort of visual tokens by bit pattern (1 CTA) ----------------
__global__ __launch_bounds__(256) void sort_kernel() {
    __shared__ unsigned hist[256];
    __shared__ unsigned offs[256];
    const int tid = threadIdx.x;
    hist[tid] = 0;
    __syncthreads();
    for (int w = tid; w < WTOK; w += 256) atomicAdd(&hist[g_bits[w]], 1u);
    __syncthreads();
    if (tid == 0) {
        unsigned acc = 0;
        for (int i = 0; i < 256; i++) { offs[i] = acc; acc += hist[i]; }
    }
    __syncthreads();
    for (int w = tid; w < WTOK; w += 256) {
        unsigned b = g_bits[w];
        unsigned pos = atomicAdd(&offs[b], 1u);
        g_perm[pos] = w;
        g_inv[w] = (int)pos;
        g_pb[pos] = b;
    }
    for (int t = tid; t < NTOK - WTOK; t += 256) {
        g_perm[WTOK + t] = WTOK + t;
        g_inv[WTOK + t] = WTOK + t;
        g_pb[WTOK + t] = 0u;
    }
}

// ---------------- tf32 mma GEMM core: 128x64 CTA tile, 2-stage, k-chunks of 16 ----------
struct GemmFrag { float c[8][4]; };

__device__ __forceinline__ void gemm320(
    const float* __restrict__ A, const float* __restrict__ B,
    int row0, int colbase, GemmFrag& F)
{
    __shared__ __align__(16) float As[2][128][18];
    __shared__ __align__(16) float Bs[2][64][18];

    const int tid = threadIdx.x;
    const int warp = tid >> 5, lane = tid & 31;
    const int g = lane >> 2, ctg = lane & 3;
    const int wr = warp * 16;

#pragma unroll
    for (int nt = 0; nt < 8; nt++) F.c[nt][0] = F.c[nt][1] = F.c[nt][2] = F.c[nt][3] = 0.f;

    const int ar = tid >> 2;
    const int aq = (tid & 3) * 4;
    const int bn = tid & 63, bk0 = tid >> 6;

    float4 ra[2];
    float  rb[4];

    // prologue: chunk 0 -> regs
#pragma unroll
    for (int i = 0; i < 2; i++) {
        int row = row0 + ar + i * 64;
        ra[i] = make_float4(0.f, 0.f, 0.f, 0.f);
        if (row < NTOK) ra[i] = *(const float4*)&A[row * QDIM + aq];
    }
#pragma unroll
    for (int s = 0; s < 4; s++)
        rb[s] = B[(bk0 + 4 * s) * QDIM + colbase + bn];

    for (int kc = 0; kc < 20; kc++) {
        const int st = kc & 1;
        {
            const int base = (aq >> 3) * 8 + ((aq & 4) ? 1 : 0);
#pragma unroll
            for (int i = 0; i < 2; i++) {
                As[st][ar + i * 64][base + 0] = tfv(ra[i].x);
                As[st][ar + i * 64][base + 2] = tfv(ra[i].y);
                As[st][ar + i * 64][base + 4] = tfv(ra[i].z);
                As[st][ar + i * 64][base + 6] = tfv(ra[i].w);
            }
#pragma unroll
            for (int s = 0; s < 4; s++)
                Bs[st][bn][kpos(bk0 + 4 * s)] = tfv(rb[s]);
        }
        __syncthreads();
        if (kc + 1 < 20) {
            const int k0 = (kc + 1) * 16;
#pragma unroll
            for (int i = 0; i < 2; i++) {
                int row = row0 + ar + i * 64;
                ra[i] = make_float4(0.f, 0.f, 0.f, 0.f);
                if (row < NTOK) ra[i] = *(const float4*)&A[row * QDIM + k0 + aq];
            }
#pragma unroll
            for (int s = 0; s < 4; s++)
                rb[s] = B[(k0 + bk0 + 4 * s) * QDIM + colbase + bn];
        }
#pragma unroll
        for (int ks = 0; ks < 2; ks++) {
            uint2 aA = *(const uint2*)&As[st][wr + g][ks * 8 + 2 * ctg];
            uint2 aB = *(const uint2*)&As[st][wr + g + 8][ks * 8 + 2 * ctg];
            unsigned a[4] = { aA.x, aB.x, aA.y, aB.y };
#pragma unroll
            for (int nt = 0; nt < 8; nt++) {
                const uint2 b = *(const uint2*)&Bs[st][nt * 8 + g][ks * 8 + 2 * ctg];
                mma8(F.c[nt], a, b.x, b.y);
            }
        }
    }
}

// ---------------- QKV via mma: scatter into permuted token order. grid (33,15) ----------
__global__ __launch_bounds__(256) void qkv_mma_kernel(
    const float* __restrict__ x,
    const float* __restrict__ Wq, const float* __restrict__ Wk, const float* __restrict__ Wv)
{
    const int by = blockIdx.y;
    const int wsel = by / 5;
    const int colbase = (by % 5) * 64;
    const float* W = (wsel == 0) ? Wq : (wsel == 1) ? Wk : Wv;
    float* dst = (wsel == 0) ? g_q : (wsel == 1) ? g_k : g_v;

    const int row0 = blockIdx.x * 128;
    GemmFrag F;
    gemm320(x, W, row0, colbase, F);

    const int lane = threadIdx.x & 31;
    const int g = lane >> 2, ctg = lane & 3;
    const int wr = (threadIdx.x >> 5) * 16;
    const int r0 = row0 + wr + g, r1 = r0 + 8;
    const int p0 = (r0 < NTOK) ? g_inv[r0] : 0;
    const int p1 = (r1 < NTOK) ? g_inv[r1] : 0;
#pragma unroll
    for (int nt = 0; nt < 8; nt++) {
        int col = colbase + nt * 8 + 2 * ctg;
        int h = col / DHEAD, cc = col % DHEAD;   // pair never straddles head
        if (r0 < NTOK) *(float2*)&dst[(h * NTOK + p0) * DHEAD + cc] = make_float2(F.c[nt][0], F.c[nt][1]);
        if (r1 < NTOK) *(float2*)&dst[(h * NTOK + p1) * DHEAD + cc] = make_float2(F.c[nt][2], F.c[nt][3]);
    }
}

// ---------------- output projection via mma (original order). grid (33,5) ----------------
__global__ __launch_bounds__(256) void proj_mma_kernel(
    const float* __restrict__ Wo, const float* __restrict__ bo, float* __restrict__ out)
{
    const int row0 = blockIdx.x * 128;
    const int colbase = blockIdx.y * 64;
    GemmFrag F;
    gemm320(g_att, Wo, row0, colbase, F);

    const int lane = threadIdx.x & 31;
    const int g = lane >> 2, ctg = lane & 3;
    const int wr = (threadIdx.x >> 5) * 16;
    const int r0 = row0 + wr + g, r1 = r0 + 8;
#pragma unroll
    for (int nt = 0; nt < 8; nt++) {
        int col = colbase + nt * 8 + 2 * ctg;
        float2 bias = *(const float2*)&bo[col];
        if (r0 < NTOK) *(float2*)&out[r0 * QDIM + col] =
            make_float2(F.c[nt][0] + bias.x, F.c[nt][1] + bias.y);
        if (r1 < NTOK) *(float2*)&out[r1 * QDIM + col] =
            make_float2(F.c[nt][2] + bias.x, F.c[nt][3] + bias.y);
    }
}

// ---------------- flash attention: permuted space, tile skip, db K/V, 1 bar/tile ----
__global__ __launch_bounds__(256, 2) void attn_kernel() {
    __shared__ __align__(16) float Ks[2][64][42];
    __shared__ __align__(16) float Vp[2][32][80];
    __shared__ __align__(8) unsigned kb_[2][64];
    __shared__ unsigned colp[2][2];

    const int tid  = threadIdx.x;
    const int warp = tid >> 5, lane = tid & 31;
    const int g    = lane >> 2, ctg = lane & 3;
    const int qb   = blockIdx.x, head = blockIdx.y;
    const int qr0  = qb * 128;
    const int wr0  = qr0 + warp * 16;
    const bool qvis = (qr0 < WTOK);

    const float* Q = g_q + head * NTOK * DHEAD;
    const float* K = g_k + head * NTOK * DHEAD;
    const float* V = g_v + head * NTOK * DHEAD;

    const int r0g = wr0 + g, r1g = r0g + 8;
    const int diagKt = wr0 >> 6;

    unsigned qa[5][4];
#pragma unroll
    for (int ks = 0; ks < 5; ks++) {
        int c0 = ks * 8 + ctg;
        float q00 = (r0g < NTOK) ? Q[r0g * DHEAD + c0]     : 0.f;
        float q10 = (r1g < NTOK) ? Q[r1g * DHEAD + c0]     : 0.f;
        float q01 = (r0g < NTOK) ? Q[r0g * DHEAD + c0 + 4] : 0.f;
        float q11 = (r1g < NTOK) ? Q[r1g * DHEAD + c0 + 4] : 0.f;
        qa[ks][0] = f2tf(q00 * QSCALE);
        qa[ks][1] = f2tf(q10 * QSCALE);
        qa[ks][2] = f2tf(q01 * QSCALE);
        qa[ks][3] = f2tf(q11 * QSCALE);
    }
    const unsigned rb0 = (r0g < WTOK) ? g_pb[r0g] : 0u;
    const unsigned rb1 = (r1g < WTOK) ? g_pb[r1g] : 0u;
    const unsigned warpOR = __reduce_or_sync(0xffffffffu, rb0 | rb1);

    float m0 = -1e30f, m1 = -1e30f, l0 = 0.f, l1 = 0.f;
    float O[5][4] = {};

    float4 kr[3], vr[3];
    unsigned kbreg = 0, cpart = 0;

    // ---- load tile 0 into regs ----
#pragma unroll
    for (int i = 0; i < 3; i++) {
        int u = tid + 256 * i;
        kr[i] = make_float4(0.f, 0.f, 0.f, 0.f);
        vr[i] = kr[i];
        if (u < 640) {
            int j = u / 10, c4 = (u % 10) * 4;
            if (j < NTOK) {
                kr[i] = *(const float4*)&K[j * DHEAD + c4];
                vr[i] = *(const float4*)&V[j * DHEAD + c4];
            }
        }
    }
    if (warp < 2) {
        kbreg = (tid < NTOK) ? g_pb[tid] : 0u;
        cpart = __reduce_or_sync(0xffffffffu, kbreg);
    }

    for (int kt = 0; kt < 65; kt++) {
        const int k0 = kt * 64;
        const bool kvis = (k0 < WTOK);
        const int st = kt & 1;

        // ---- STS regs -> stage st ----
#pragma unroll
        for (int i = 0; i < 3; i++) {
            int u = tid + 256 * i;
            if (u < 640) {
                int j = u / 10, c4 = (u % 10) * 4;
                int b8 = c4 >> 3;
                float* krp = &Ks[st][j][b8 * 8 + ((c4 & 4) ? 1 : 0)];
                krp[0] = tfv(kr[i].x); krp[2] = tfv(kr[i].y);
                krp[4] = tfv(kr[i].z); krp[6] = tfv(kr[i].w);
                float* vrp = &Vp[st][(j >> 3) * 4 + (j & 3)][c4 * 2 + ((j >> 2) & 1)];
                vrp[0] = tfv(vr[i].x); vrp[2] = tfv(vr[i].y);
                vrp[4] = tfv(vr[i].z); vrp[6] = tfv(vr[i].w);
            }
        }
        if (warp < 2) {
            kb_[st][warp * 32 + lane] = kbreg;
            if (lane == 0) colp[st][warp] = cpart;
        }
        __syncthreads();

        // ---- prefetch tile kt+1 -> regs (hidden behind compute) ----
        if (kt + 1 < 65) {
            const int nk0 = (kt + 1) * 64;
#pragma unroll
            for (int i = 0; i < 3; i++) {
                int u = tid + 256 * i;
                kr[i] = make_float4(0.f, 0.f, 0.f, 0.f);
                vr[i] = kr[i];
                if (u < 640) {
                    int j = u / 10, c4 = (u % 10) * 4;
                    int key = nk0 + j;
                    if (key < NTOK) {
                        kr[i] = *(const float4*)&K[key * DHEAD + c4];
                        vr[i] = *(const float4*)&V[key * DHEAD + c4];
                    }
                }
            }
            if (warp < 2) {
                int key = nk0 + warp * 32 + lane;
                kbreg = (key < NTOK) ? g_pb[key] : 0u;
                cpart = __reduce_or_sync(0xffffffffu, kbreg);
            }
        }

        // ---- exact-safe warp-level tile skip ----
        if (qvis && kvis && kt != diagKt && ((warpOR & (colp[st][0] | colp[st][1])) == 0u))
            continue;

        // ---- S = Q K^T ----
        float c[8][4];
#pragma unroll
        for (int nt = 0; nt < 8; nt++) { c[nt][0] = c[nt][1] = c[nt][2] = c[nt][3] = 0.f; }
#pragma unroll
        for (int nt = 0; nt < 8; nt++) {
#pragma unroll
            for (int ks = 0; ks < 5; ks++) {
                const uint2 b = *(const uint2*)&Ks[st][nt * 8 + g][ks * 8 + 2 * ctg];
                mma8(c[nt], qa[ks], b.x, b.y);
            }
        }

        // ---- mask ----
        if (qvis && kvis) {
            if (kt == diagKt) {
                const int ri0 = r0g - k0, ri1 = r1g - k0;
#pragma unroll
                for (int nt = 0; nt < 8; nt++) {
                    int j0 = nt * 8 + 2 * ctg;
                    uint2 cb = *(const uint2*)&kb_[st][j0];
                    if (!((rb0 & cb.x) || (ri0 == j0)))     c[nt][0] = -1e30f;
                    if (!((rb0 & cb.y) || (ri0 == j0 + 1))) c[nt][1] = -1e30f;
                    if (!((rb1 & cb.x) || (ri1 == j0)))     c[nt][2] = -1e30f;
                    if (!((rb1 & cb.y) || (ri1 == j0 + 1))) c[nt][3] = -1e30f;
                }
            } else {
#pragma unroll
                for (int nt = 0; nt < 8; nt++) {
                    uint2 cb = *(const uint2*)&kb_[st][nt * 8 + 2 * ctg];
                    if (!(rb0 & cb.x)) c[nt][0] = -1e30f;
                    if (!(rb0 & cb.y)) c[nt][1] = -1e30f;
                    if (!(rb1 & cb.x)) c[nt][2] = -1e30f;
                    if (!(rb1 & cb.y)) c[nt][3] = -1e30f;
                }
            }
        } else if (qvis) {
#pragma unroll
            for (int nt = 0; nt < 8; nt++) {
                int col0 = k0 + nt * 8 + 2 * ctg;
                int t0 = col0 - WTOK, t1 = t0 + 1;
                bool gr0 = (t0 >= 8 && t0 < 24), gr1 = (t1 >= 8 && t1 < 24);
                if (!((col0     < NTOK) && (gr0 || ((rb0 >> (t0 & 7)) & 1)))) c[nt][0] = -1e30f;
                if (!((col0 + 1 < NTOK) && (gr1 || ((rb0 >> (t1 & 7)) & 1)))) c[nt][1] = -1e30f;
                if (!((col0     < NTOK) && (gr0 || ((rb1 >> (t0 & 7)) & 1)))) c[nt][2] = -1e30f;
                if (!((col0 + 1 < NTOK) && (gr1 || ((rb1 >> (t1 & 7)) & 1)))) c[nt][3] = -1e30f;
            }
        } else if (kvis) {
            int t0 = r0g - WTOK, t1 = r1g - WTOK;
            bool gr0 = (t0 >= 8 && t0 < 24), gr1 = (t1 >= 8 && t1 < 24);
#pragma unroll
            for (int nt = 0; nt < 8; nt++) {
                uint2 cb = *(const uint2*)&kb_[st][nt * 8 + 2 * ctg];
                if (!(gr0 || ((cb.x >> (t0 & 7)) & 1))) c[nt][0] = -1e30f;
                if (!(gr1 || ((cb.x >> (t1 & 7)) & 1))) c[nt][2] = -1e30f;
                if (!(gr0 || ((cb.y >> (t0 & 7)) & 1))) c[nt][1] = -1e30f;
                if (!(gr1 || ((cb.y >> (t1 & 7)) & 1))) c[nt][3] = -1e30f;
            }
        } else {
#pragma unroll
            for (int nt = 0; nt < 8; nt++) {
                int col0 = k0 + nt * 8 + 2 * ctg;
                if (!(col0     < NTOK)) { c[nt][0] = -1e30f; c[nt][2] = -1e30f; }
                if (!(col0 + 1 < NTOK)) { c[nt][1] = -1e30f; c[nt][3] = -1e30f; }
            }
        }

        // ---- online softmax (base 2) ----
        float mx0 = c[0][0], mx1 = c[0][2];
#pragma unroll
        for (int nt = 0; nt < 8; nt++) {
            mx0 = fmaxf(mx0, fmaxf(c[nt][0], c[nt][1]));
            mx1 = fmaxf(mx1, fmaxf(c[nt][2], c[nt][3]));
        }
        mx0 = fmaxf(mx0, __shfl_xor_sync(0xffffffffu, mx0, 1));
        mx0 = fmaxf(mx0, __shfl_xor_sync(0xffffffffu, mx0, 2));
        mx1 = fmaxf(mx1, __shfl_xor_sync(0xffffffffu, mx1, 1));
        mx1 = fmaxf(mx1, __shfl_xor_sync(0xffffffffu, mx1, 2));

        float nm0 = fmaxf(m0, mx0), nm1 = fmaxf(m1, mx1);
        float f0 = ex2f(m0 - nm0), f1 = ex2f(m1 - nm1);
        m0 = nm0; m1 = nm1;

        float s0 = 0.f, s1 = 0.f;
#pragma unroll
        for (int nt = 0; nt < 8; nt++) {
            c[nt][0] = tfv(ex2f(c[nt][0] - nm0));
            c[nt][1] = tfv(ex2f(c[nt][1] - nm0));
            c[nt][2] = tfv(ex2f(c[nt][2] - nm1));
            c[nt][3] = tfv(ex2f(c[nt][3] - nm1));
            s0 += c[nt][0] + c[nt][1];
            s1 += c[nt][2] + c[nt][3];
        }
        s0 += __shfl_xor_sync(0xffffffffu, s0, 1);
        s0 += __shfl_xor_sync(0xffffffffu, s0, 2);
        s1 += __shfl_xor_sync(0xffffffffu, s1, 1);
        s1 += __shfl_xor_sync(0xffffffffu, s1, 2);
        l0 = l0 * f0 + s0;
        l1 = l1 * f1 + s1;

#pragma unroll
        for (int nt = 0; nt < 5; nt++) {
            O[nt][0] *= f0; O[nt][1] *= f0; O[nt][2] *= f1; O[nt][3] *= f1;
        }

        // ---- O += P V : C-layout -> A-layout via quad shuffles ----
        const int srcA = (lane & ~3) | (ctg >> 1);
        const int srcB = srcA + 2;
        const bool hi = (ctg & 1);
#pragma unroll
        for (int kk = 0; kk < 8; kk++) {
            float x0 = __shfl_sync(0xffffffffu, c[kk][0], srcA);
            float x1 = __shfl_sync(0xffffffffu, c[kk][1], srcA);
            float x2 = __shfl_sync(0xffffffffu, c[kk][2], srcA);
            float x3 = __shfl_sync(0xffffffffu, c[kk][3], srcA);
            float y0 = __shfl_sync(0xffffffffu, c[kk][0], srcB);
            float y1 = __shfl_sync(0xffffffffu, c[kk][1], srcB);
            float y2 = __shfl_sync(0xffffffffu, c[kk][2], srcB);
            float y3 = __shfl_sync(0xffffffffu, c[kk][3], srcB);
            unsigned a[4];
            a[0] = __float_as_uint(hi ? x1 : x0);
            a[1] = __float_as_uint(hi ? x3 : x2);
            a[2] = __float_as_uint(hi ? y1 : y0);
            a[3] = __float_as_uint(hi ? y3 : y2);
#pragma unroll
            for (int nt = 0; nt < 5; nt++) {
                const uint2 b = *(const uint2*)&Vp[st][kk * 4 + ctg][(nt * 8 + g) * 2];
                mma8(O[nt], a, b.x, b.y);
            }
        }
    }

    // ---- epilogue: gather back to original token order ----
    float il0 = 1.f / l0, il1 = 1.f / l1;
    const int o0 = (r0g < NTOK) ? g_perm[r0g] : 0;
    const int o1 = (r1g < NTOK) ? g_perm[r1g] : 0;
#pragma unroll
    for (int nt = 0; nt < 5; nt++) {
        int col = head * DHEAD + nt * 8 + 2 * ctg;
        if (r0g < NTOK) {
            float2 o = make_float2(O[nt][0] * il0, O[nt][1] * il0);
            *(float2*)&g_att[o0 * QDIM + col] = o;
        }
        if (r1g < NTOK) {
            float2 o = make_float2(O[nt][2] * il1, O[nt][3] * il1);
            *(float2*)&g_att[o1 * QDIM + col] = o;
        }
    }
}

// ---------------- launch ----------------
extern "C" void kernel_launch(void* const* d_in, const int* in_sizes, int n_in,
                              void* d_out, int out_size) {
    const float* x  = (const float*)d_in[0];
    const float* am = (const float*)d_in[1];
    const float* Wq = (const float*)d_in[2];
    const float* Wk = (const float*)d_in[3];
    const float* Wv = (const float*)d_in[4];
    const float* Wo = (const float*)d_in[5];
    const float* bo = (const float*)d_in[6];
    float* out = (float*)d_out;

    bits_kernel<<<16, 256>>>(am);
    sort_kernel<<<1, 256>>>();
    qkv_mma_kernel<<<dim3(33, 15), 256>>>(x, Wq, Wk, Wv);
    attn_kernel<<<dim3(33, NHEAD), 256>>>();
    proj_mma_kernel<<<dim3(33, 5), 256>>>(Wo, bo, out);
}